// round 3
// baseline (speedup 1.0000x reference)
#include <cuda_runtime.h>
#include <math.h>

#define DD 96
#define NPART 48

__device__ double g_G[DD * DD];
__device__ double g_pk[NPART];

// ---------------------------------------------------------------------------
// G = I - P P^T. 36 blocks x 256 threads, one output element per thread.
// 4-way split accumulators to break the dependent DFMA chain.
// ---------------------------------------------------------------------------
__global__ void build_G_kernel(const float* __restrict__ P) {
    int idx = blockIdx.x * blockDim.x + threadIdx.x;  // 36*256 = 9216
    int i = idx / DD;
    int j = idx - i * DD;
    const float* __restrict__ Pi = P + i * NPART;
    const float* __restrict__ Pj = P + j * NPART;
    double a0 = 0.0, a1 = 0.0, a2 = 0.0, a3 = 0.0;
#pragma unroll
    for (int t = 0; t < NPART; t += 4) {
        a0 = fma((double)Pi[t],     (double)Pj[t],     a0);
        a1 = fma((double)Pi[t + 1], (double)Pj[t + 1], a1);
        a2 = fma((double)Pi[t + 2], (double)Pj[t + 2], a2);
        a3 = fma((double)Pi[t + 3], (double)Pj[t + 3], a3);
    }
    g_G[idx] = ((i == j) ? 1.0 : 0.0) - ((a0 + a1) + (a2 + a3));
}

// ---------------------------------------------------------------------------
// Per-k symmetric elimination, matrix in registers.
// Thread (ty,tx) owns A[r][c] for r = ty+8*jr (12 rows), c = tx+32*jc (3 cols).
// Symmetry => elimination factors come from the pivot ROW only:
//   l_r = urow[r] * inv.  One pivot-row publish + one barrier per step.
// Pivot lookahead: p_{i+1} = diag[i+1] - urow[i+1]^2 * inv  (computed by all
// threads redundantly), so 1/p overlaps the update FMAs.
// ---------------------------------------------------------------------------
__global__ void __launch_bounds__(256, 1)
lu_probs_kernel(const int* __restrict__ occ, float* __restrict__ out) {
    __shared__ double urow[2][DD];   // double-buffered pivot row
    __shared__ double s_diag[DD];    // lookahead diagonal values
    __shared__ double pivs[DD];      // final pivots
    __shared__ double sc[2][DD];     // prefix-product scan
    __shared__ int s_occ[NPART];
    __shared__ int s_nb[DD];

    const int k = blockIdx.x;
    const int m = DD - NPART + k + 1;  // xmax = 49 + k
    const int tid = threadIdx.x;
    const int tx = tid & 31;
    const int ty = tid >> 5;

    if (tid < NPART) s_occ[tid] = occ[tid];
    if (tid < DD) s_nb[tid] = 0;

    // Load owned elements of G (coalesced: lane-consecutive columns).
    double a[12][3];
#pragma unroll
    for (int jr = 0; jr < 12; jr++) {
        const int r = ty + 8 * jr;
#pragma unroll
        for (int jc = 0; jc < 3; jc++)
            a[jr][jc] = g_G[r * DD + tx + 32 * jc];
    }
    __syncthreads();
    if (tid < k) s_nb[s_occ[tid]] = 1;  // occupancy of particles < k
    __syncthreads();

    // Diagonal subtraction + initial publishes of diag[0], diag[1].
#pragma unroll
    for (int jr = 0; jr < 12; jr++) {
        const int r = ty + 8 * jr;
#pragma unroll
        for (int jc = 0; jc < 3; jc++) {
            const int c = tx + 32 * jc;
            if (r == c) {
                if (s_nb[r]) a[jr][jc] -= 1.0;
                if (r == 0) s_diag[0] = a[jr][jc];
                if (r == 1) s_diag[1] = a[jr][jc];
            }
        }
    }
    // Publish pivot row 0 into buffer 0 (owner warp ty==0, jr==0).
    if (ty == 0) {
#pragma unroll
        for (int jc = 0; jc < 3; jc++) urow[0][tx + 32 * jc] = a[0][jc];
    }
    __syncthreads();

    double inv = 1.0 / s_diag[0];
    const int mstop = m - 1;

    for (int i = 0; i < mstop; i++) {
        const int p = i & 1;
        const double* __restrict__ ur = urow[p];
        double* __restrict__ un = urow[p ^ 1];

        // Lookahead pivot for step i+1 (valid via symmetry), overlaps update.
        const double w = ur[i + 1];
        const double pnext = s_diag[i + 1] - w * w * inv;
        const double inv_next = 1.0 / pnext;

        // Column values of the pivot row, masked to active columns.
        double uc[3];
#pragma unroll
        for (int jc = 0; jc < 3; jc++) {
            const int c = tx + 32 * jc;
            uc[jc] = (c > i) ? ur[c] : 0.0;
        }

        // Rank-1 update of owned active rows (warp-uniform branch on r>i).
#pragma unroll
        for (int jr = 0; jr < 12; jr++) {
            const int r = ty + 8 * jr;
            if (r > i) {
                const double l = ur[r] * inv;
#pragma unroll
                for (int jc = 0; jc < 3; jc++)
                    a[jr][jc] = fma(-l, uc[jc], a[jr][jc]);
            }
        }

        // Publish updated row i+1 (final) into the other buffer.
        if (ty == ((i + 1) & 7)) {
#pragma unroll
            for (int jr = 0; jr < 12; jr++)
                if (ty + 8 * jr == i + 1) {
#pragma unroll
                    for (int jc = 0; jc < 3; jc++)
                        un[tx + 32 * jc] = a[jr][jc];
                }
        }
        // Publish diagonal (i+2,i+2) post-step-i value for next lookahead.
        if (i + 2 < DD && ty == ((i + 2) & 7) && tx == ((i + 2) & 31)) {
            const int jcp = (i + 2) >> 5;
#pragma unroll
            for (int jr = 0; jr < 12; jr++)
                if (ty + 8 * jr == i + 2) {
                    const double v =
                        (jcp == 0) ? a[jr][0] : (jcp == 1) ? a[jr][1] : a[jr][2];
                    s_diag[i + 2] = v;
                }
        }

        inv = inv_next;
        __syncthreads();
    }

    // Pivots are the final diagonal registers (rows freeze at their step).
#pragma unroll
    for (int jr = 0; jr < 12; jr++) {
        const int r = ty + 8 * jr;
#pragma unroll
        for (int jc = 0; jc < 3; jc++) {
            const int c = tx + 32 * jc;
            if (r == c) pivs[r] = a[jr][jc];
        }
    }
    __syncthreads();

    const int xmin = (k == 0) ? 0 : s_occ[k - 1] + 1;

    // Inclusive prefix product of pivots masked to [xmin, m).
    if (tid < DD) sc[0][tid] = (tid >= xmin && tid < m) ? pivs[tid] : 1.0;
    __syncthreads();
    int src = 0;
    for (int off = 1; off < DD; off <<= 1) {
        if (tid < DD) {
            double v = sc[src][tid];
            if (tid >= off) v *= sc[src][tid - off];
            sc[src ^ 1][tid] = v;
        }
        __syncthreads();
        src ^= 1;
    }

    if (tid < DD) {
        const int x = tid;
        double pr = 0.0;
        if (x >= xmin && x < m) {
            const double S = (x == xmin) ? 1.0 : sc[src][x - 1];
            pr = -S * (pivs[x] - 1.0);
            if (!(fabs(pr) > 1e-15)) pr = 0.0;
        }
        out[k * DD + x] = (float)pr;
        if (x == s_occ[k]) g_pk[k] = pr;
    }
}

// ---------------------------------------------------------------------------
// prob_sample = prod_k p_k.
// ---------------------------------------------------------------------------
__global__ void prod_kernel(float* __restrict__ out) {
    const int t = threadIdx.x;  // 32
    double v = g_pk[t];
    if (t < 16) v *= g_pk[32 + t];
#pragma unroll
    for (int off = 16; off > 0; off >>= 1)
        v *= __shfl_xor_sync(0xFFFFFFFFu, v, off);
    if (t == 0) out[NPART * DD] = (float)v;
}

extern "C" void kernel_launch(void* const* d_in, const int* in_sizes, int n_in,
                              void* d_out, int out_size) {
    const float* P;
    const int* occ;
    if (in_sizes[0] == DD * NPART) {
        P = (const float*)d_in[0];
        occ = (const int*)d_in[1];
    } else {
        P = (const float*)d_in[1];
        occ = (const int*)d_in[0];
    }
    float* out = (float*)d_out;

    build_G_kernel<<<36, 256>>>(P);
    lu_probs_kernel<<<NPART, 256>>>(occ, out);
    prod_kernel<<<1, 32>>>(out);
}

// round 4
// speedup vs baseline: 1.7209x; 1.7209x over previous
#include <cuda_runtime.h>
#include <math.h>

#define DD 96
#define NPART 48
#define PITCH 96

__device__ double g_G[DD * DD];
__device__ double g_pk[NPART];

// ---------------------------------------------------------------------------
// Fast fp64 reciprocal: rcp.approx.f32 seed + 2 Newton steps (~2^-52).
// ---------------------------------------------------------------------------
__device__ __forceinline__ double fast_recip(double p) {
    float pf = (float)p;
    float rf;
    asm("rcp.approx.f32 %0, %1;" : "=f"(rf) : "f"(pf));
    double r = (double)rf;
    r = r * __fma_rn(-p, r, 2.0);
    r = r * __fma_rn(-p, r, 2.0);
    return r;
}

// ---------------------------------------------------------------------------
// G = I - P P^T. 36 blocks x 256 threads; P staged transposed in shared.
// ---------------------------------------------------------------------------
__global__ void build_G_kernel(const float* __restrict__ P) {
    __shared__ float Pt[NPART][DD];  // Pt[t][i] = P[i*NPART+t]
    const int tid = threadIdx.x;
    for (int idx = tid; idx < DD * NPART; idx += 256) {
        int r = idx / NPART;
        int t = idx - r * NPART;
        Pt[t][r] = P[idx];
    }
    __syncthreads();
    const int idx = blockIdx.x * 256 + tid;
    const int i = idx / DD;
    const int j = idx - i * DD;
    double a0 = 0.0, a1 = 0.0, a2 = 0.0, a3 = 0.0;
#pragma unroll
    for (int t = 0; t < NPART; t += 4) {
        a0 = fma((double)Pt[t][i],     (double)Pt[t][j],     a0);
        a1 = fma((double)Pt[t + 1][i], (double)Pt[t + 1][j], a1);
        a2 = fma((double)Pt[t + 2][i], (double)Pt[t + 2][j], a2);
        a3 = fma((double)Pt[t + 3][i], (double)Pt[t + 3][j], a3);
    }
    g_G[idx] = ((i == j) ? 1.0 : 0.0) - ((a0 + a1) + (a2 + a3));
}

// ---------------------------------------------------------------------------
// Per-k symmetric elimination on the UPPER TRIANGLE of the leading m x m block
// (m = 49+k), matrix in shared.  One barrier per step.
//   A[r][c] -= A[i][r]*inv * A[i][c]   for i < r <= c < m
// The warp owning row i+1 finalizes it; the lane hitting the diagonal computes
// the next pivot + its reciprocal (fast Newton) and publishes before the step
// barrier -> the fp64 divide overlaps the trailing update.
// ---------------------------------------------------------------------------
__global__ void __launch_bounds__(256, 1)
lu_probs_kernel(const int* __restrict__ occ, float* __restrict__ out) {
    extern __shared__ double A_[];       // PITCH * DD doubles (73728 B)
    __shared__ double s_piv[DD];
    __shared__ double s_inv[2];
    __shared__ double sc[2][DD];
    __shared__ int s_occ[NPART];

    const int k = blockIdx.x;
    const int m = DD - NPART + k + 1;    // 49 + k
    const int tid = threadIdx.x;         // 256
    const int tx = tid & 31;
    const int ty = tid >> 5;             // warp id, rows r ≡ ty (mod 8)

    if (tid < NPART) s_occ[tid] = occ[tid];

    const int c0 = tx, c1 = tx + 32, c2 = tx + 64;

    // Load upper triangle of leading m x m block of G.
    for (int r = ty; r < m; r += 8) {
        if (c0 >= r && c0 < m) A_[r * PITCH + c0] = g_G[r * DD + c0];
        if (c1 >= r && c1 < m) A_[r * PITCH + c1] = g_G[r * DD + c1];
        if (c2 >= r && c2 < m) A_[r * PITCH + c2] = g_G[r * DD + c2];
    }
    __syncthreads();
    // Diagonal occupancy subtraction (distinct positions -> race-free).
    if (tid < k) {
        int p = s_occ[tid];
        if (p < m) A_[p * PITCH + p] -= 1.0;
    }
    __syncthreads();
    if (tid == 0) {
        double p0 = A_[0];
        s_piv[0] = p0;
        s_inv[0] = fast_recip(p0);
    }
    __syncthreads();

    const int mstop = m - 1;
    for (int i = 0; i < mstop; i++) {
        const double inv = s_inv[i & 1];
        const double* __restrict__ urow = &A_[i * PITCH];
        // Pivot-row values for this lane's columns (reused across rows).
        const double u0 = urow[c0];
        const double u1 = urow[c1];
        const double u2 = urow[c2];

        // Rows r = ty + 8*jr with i < r < m (warp-uniform bounds).
        int jr = (i + 8 - ty) >> 3;          // first r >= i+1 in this residue
        const int jrmax = (mstop - ty) >> 3; // last r <= m-1
        const int ip1 = i + 1;
        for (; jr <= jrmax; jr++) {
            const int r = ty + 8 * jr;
            const double l = urow[r] * inv;
            double* __restrict__ arow = &A_[r * PITCH];
            double v0 = 0.0, v1 = 0.0, v2 = 0.0;
            if (c0 >= r) arow[c0] = v0 = __fma_rn(-l, u0, arow[c0]);
            if (c1 >= r) arow[c1] = v1 = __fma_rn(-l, u1, arow[c1]);
            if (c2 >= r) arow[c2] = v2 = __fma_rn(-l, u2, arow[c2]);
            if (r == ip1) {                   // warp-uniform: owner warp only
                if (tx == (ip1 & 31)) {       // diagonal lane
                    const int jcp = ip1 >> 5;
                    const double pv = (jcp == 0) ? v0 : (jcp == 1) ? v1 : v2;
                    s_piv[ip1] = pv;
                    s_inv[ip1 & 1] = fast_recip(pv);
                }
            }
        }
        __syncthreads();
    }

    const int xmin = (k == 0) ? 0 : s_occ[k - 1] + 1;

    // Inclusive prefix product of pivots masked to [xmin, m).
    if (tid < DD) sc[0][tid] = (tid >= xmin && tid < m) ? s_piv[tid] : 1.0;
    __syncthreads();
    int src = 0;
    for (int off = 1; off < DD; off <<= 1) {
        if (tid < DD) {
            double v = sc[src][tid];
            if (tid >= off) v *= sc[src][tid - off];
            sc[src ^ 1][tid] = v;
        }
        __syncthreads();
        src ^= 1;
    }

    if (tid < DD) {
        const int x = tid;
        double pr = 0.0;
        if (x >= xmin && x < m) {
            const double S = (x == xmin) ? 1.0 : sc[src][x - 1];
            pr = -S * (s_piv[x] - 1.0);
            if (!(fabs(pr) > 1e-15)) pr = 0.0;
        }
        out[k * DD + x] = (float)pr;
        if (x == s_occ[k]) g_pk[k] = pr;
    }
}

// ---------------------------------------------------------------------------
// prob_sample = prod_k p_k.
// ---------------------------------------------------------------------------
__global__ void prod_kernel(float* __restrict__ out) {
    const int t = threadIdx.x;  // 32
    double v = g_pk[t];
    if (t < 16) v *= g_pk[32 + t];
#pragma unroll
    for (int off = 16; off > 0; off >>= 1)
        v *= __shfl_xor_sync(0xFFFFFFFFu, v, off);
    if (t == 0) out[NPART * DD] = (float)v;
}

extern "C" void kernel_launch(void* const* d_in, const int* in_sizes, int n_in,
                              void* d_out, int out_size) {
    const float* P;
    const int* occ;
    if (in_sizes[0] == DD * NPART) {
        P = (const float*)d_in[0];
        occ = (const int*)d_in[1];
    } else {
        P = (const float*)d_in[1];
        occ = (const int*)d_in[0];
    }
    float* out = (float*)d_out;

    const int smem = PITCH * DD * (int)sizeof(double);  // 73728 B
    cudaFuncSetAttribute(lu_probs_kernel,
                         cudaFuncAttributeMaxDynamicSharedMemorySize, smem);

    build_G_kernel<<<36, 256>>>(P);
    lu_probs_kernel<<<NPART, 256, smem>>>(occ, out);
    prod_kernel<<<1, 32>>>(out);
}

// round 8
// speedup vs baseline: 3.2669x; 1.8984x over previous
#include <cuda_runtime.h>
#include <math.h>

#define DD 96
#define NPART 48
#define PITCH 97

__device__ double g_G[DD * DD];
__device__ double g_pk[NPART];

// Fast fp64 reciprocal: f32 rcp seed + 2 fp64 Newton steps (~2^-48 rel).
__device__ __forceinline__ double fast_recip(double p) {
    float pf = (float)p;
    float rf;
    asm("rcp.approx.f32 %0, %1;" : "=f"(rf) : "f"(pf));
    double r = (double)rf;
    r = r * __fma_rn(-p, r, 2.0);
    r = r * __fma_rn(-p, r, 2.0);
    return r;
}

// ---------------------------------------------------------------------------
// G = I - P P^T. 96 blocks x 96 threads (round-2 structure, best measured),
// with 4-way split accumulators to break the 48-deep dependent chain.
// ---------------------------------------------------------------------------
__global__ void build_G_kernel(const float* __restrict__ P) {
    __shared__ float Pt[NPART][DD];  // Pt[t][i] = P[i*NPART+t]
    const int i = blockIdx.x;
    const int tid = threadIdx.x;  // 96

    for (int idx = tid; idx < DD * NPART; idx += DD) {
        int r = idx / NPART;
        int t = idx - r * NPART;
        Pt[t][r] = P[idx];
    }
    __syncthreads();

    const int j = tid;
    double a0 = 0.0, a1 = 0.0, a2 = 0.0, a3 = 0.0;
#pragma unroll
    for (int t = 0; t < NPART; t += 4) {
        a0 = __fma_rn((double)Pt[t][i],     (double)Pt[t][j],     a0);
        a1 = __fma_rn((double)Pt[t + 1][i], (double)Pt[t + 1][j], a1);
        a2 = __fma_rn((double)Pt[t + 2][i], (double)Pt[t + 2][j], a2);
        a3 = __fma_rn((double)Pt[t + 3][i], (double)Pt[t + 3][j], a3);
    }
    g_G[i * DD + j] = ((i == j) ? 1.0 : 0.0) - ((a0 + a1) + (a2 + a3));
}

// ---------------------------------------------------------------------------
// Per-k unpivoted symmetric elimination of the leading m x m block (m = 49+k),
// full-rectangle update (round-2 memory pattern), ONE barrier per step.
// Warp 0: updates row i+1 only, captures the new diagonal (= pivot pi_{i+1})
// in-register, computes its reciprocal (fast Newton) and publishes it to a
// 2-slot ring read the NEXT step (barrier-separated -> race-free).
// Warps 1..7: rows i+2..m-1, stride 7.  Factors l_r = A[i][r]*inv (symmetry).
// ---------------------------------------------------------------------------
__global__ void __launch_bounds__(256, 1)
lu_probs_kernel(const int* __restrict__ occ, float* __restrict__ out) {
    extern __shared__ double A_[];   // [DD][PITCH]
    __shared__ double s_piv[DD];
    __shared__ double s_inv[2];
    __shared__ double sc[2][DD];
    __shared__ int s_occ[NPART];

    const int k = blockIdx.x;
    const int m = DD - NPART + k + 1;   // 49 + k
    const int tid = threadIdx.x;        // 256
    const int tx = tid & 31;
    const int ty = tid >> 5;

    if (tid < NPART) s_occ[tid] = occ[tid];

    // Load leading m x m block of G.
    for (int r = ty; r < m; r += 8)
        for (int c = tx; c < m; c += 32)
            A_[r * PITCH + c] = g_G[r * DD + c];
    __syncthreads();
    if (tid < k) {                      // distinct positions -> race-free
        int p = s_occ[tid];
        if (p < m) A_[p * PITCH + p] -= 1.0;
    }
    __syncthreads();
    if (tid == 0) {
        double p0 = A_[0];
        s_piv[0] = p0;
        s_inv[0] = fast_recip(p0);
    }
    __syncthreads();

    const int mstop = m - 1;
    for (int i = 0; i < mstop; i++) {
        const double inv0 = s_inv[i & 1];
        const double* __restrict__ urow = &A_[i * PITCH];

        if (ty == 0) {
            // Warp 0: update row i+1 only; lane tx==0's first element (c=i+1)
            // IS the next pivot after this update.
            const int rp = i + 1;
            const double l = urow[rp] * inv0;
            double* __restrict__ arow = &A_[rp * PITCH];
            double pcap = 0.0;
            for (int c = i + 1 + tx; c < m; c += 32) {
                double v = __fma_rn(-l, urow[c], arow[c]);
                arow[c] = v;
                if (c == rp) pcap = v;   // true only for tx==0, first iter
            }
            if (tx == 0) {
                s_piv[rp] = pcap;
                s_inv[rp & 1] = fast_recip(pcap);
            }
        } else {
            // Warps 1..7: rows i+2 .. m-1, stride 7 (start i+1+ty covers i+2..i+8).
            for (int r = i + 1 + ty; r < m; r += 7) {
                const double l = urow[r] * inv0;
                double* __restrict__ arow = &A_[r * PITCH];
                for (int c = i + 1 + tx; c < m; c += 32)
                    arow[c] = __fma_rn(-l, urow[c], arow[c]);
            }
        }
        __syncthreads();
    }

    const int xmin = (k == 0) ? 0 : s_occ[k - 1] + 1;

    // Inclusive prefix product of pivots masked to [xmin, m).
    if (tid < DD) sc[0][tid] = (tid >= xmin && tid < m) ? s_piv[tid] : 1.0;
    __syncthreads();
    int src = 0;
    for (int off = 1; off < DD; off <<= 1) {
        if (tid < DD) {
            double v = sc[src][tid];
            if (tid >= off) v *= sc[src][tid - off];
            sc[src ^ 1][tid] = v;
        }
        __syncthreads();
        src ^= 1;
    }

    if (tid < DD) {
        const int x = tid;
        double pr = 0.0;
        if (x >= xmin && x < m) {
            const double S = (x == xmin) ? 1.0 : sc[src][x - 1];
            pr = -S * (s_piv[x] - 1.0);
            if (!(fabs(pr) > 1e-15)) pr = 0.0;
        }
        out[k * DD + x] = (float)pr;
        if (x == s_occ[k]) g_pk[k] = pr;
    }
}

// ---------------------------------------------------------------------------
// prob_sample = prod_k p_k.
// ---------------------------------------------------------------------------
__global__ void prod_kernel(float* __restrict__ out) {
    const int t = threadIdx.x;  // 32
    double v = g_pk[t];
    if (t < 16) v *= g_pk[32 + t];
#pragma unroll
    for (int off = 16; off > 0; off >>= 1)
        v *= __shfl_xor_sync(0xFFFFFFFFu, v, off);
    if (t == 0) out[NPART * DD] = (float)v;
}

extern "C" void kernel_launch(void* const* d_in, const int* in_sizes, int n_in,
                              void* d_out, int out_size) {
    const float* P;
    const int* occ;
    if (in_sizes[0] == DD * NPART) {
        P = (const float*)d_in[0];
        occ = (const int*)d_in[1];
    } else {
        P = (const float*)d_in[1];
        occ = (const int*)d_in[0];
    }
    float* out = (float*)d_out;

    const int smem = DD * PITCH * (int)sizeof(double);  // 74496 B
    cudaFuncSetAttribute(lu_probs_kernel,
                         cudaFuncAttributeMaxDynamicSharedMemorySize, smem);

    build_G_kernel<<<DD, DD>>>(P);
    lu_probs_kernel<<<NPART, 256, smem>>>(occ, out);
    prod_kernel<<<1, 32>>>(out);
}